// round 1
// baseline (speedup 1.0000x reference)
#include <cuda_runtime.h>
#include <cstdint>
#include <cstddef>

#define D_TOTAL   786432
#define TILE      128
#define N_TILES   (D_TOTAL / TILE)   // 6144
#define BATCH     64
#define XPITCH    130                // floats per x smem row (pad for banks)
#define WPITCH    52                 // floats per transposed-W smem row (24 k * 2 + pad, 16B aligned)
#define NBLK      296
#define NTHREADS  256
#define NJ        25                 // 24 dots + sumsq

// per-block partial results: [NBLK][BATCH][NJ]
__device__ float g_partial[NBLK * BATCH * NJ];

__device__ __forceinline__ float fold2(unsigned long long v) {
    return __uint_as_float((unsigned)v) + __uint_as_float((unsigned)(v >> 32));
}

// packed dual fp32 FMA (Blackwell f32x2)
#define FFMA2(accv, av, bv) asm("fma.rn.f32x2 %0, %1, %2, %0;" : "+l"(accv) : "l"(av), "l"(bv))

__global__ void __launch_bounds__(NTHREADS, 2)
dot_kernel(const float* __restrict__ x, const float* __restrict__ wn,
           const float* __restrict__ Wpre, const float* __restrict__ Wpost,
           const float* __restrict__ Wres)
{
    __shared__ float xs[BATCH * XPITCH];   // 33280 B
    __shared__ float ws[64 * WPITCH];      // 13312 B  (d-pair major, wn folded in)

    const int t    = threadIdx.x;
    const int lane = t & 31;
    const int w    = t >> 5;
    const int kg   = w & 1;    // k-group: k = kg*12 .. +11
    const int dg   = w >> 1;   // d-group: pairs dg*16 .. +15

    unsigned long long acc[24];      // [b2*12 + j] : b2=0 -> b=lane, b2=1 -> b=lane+32
#pragma unroll
    for (int i = 0; i < 24; i++) acc[i] = 0ull;
    unsigned long long ss0 = 0ull, ss1 = 0ull;

    for (int tile = blockIdx.x; tile < N_TILES; tile += NBLK) {
        const int d0 = tile * TILE;
        __syncthreads();   // previous compute done before restaging

        // ---- stage x: 64 rows x 64 float2. lanes span d -> coalesced global,
        //      STS banks (2*lane) -> 2-phase minimum.
#pragma unroll
        for (int it = 0; it < 16; it++) {
            int idx = it * NTHREADS + t;
            int d2  = idx & 63;
            int row = idx >> 6;
            float2 v = *(const float2*)(x + (size_t)row * D_TOTAL + d0 + 2 * d2);
            *(float2*)(xs + row * XPITCH + 2 * d2) = v;
        }

        // ---- stage W transposed to d-pair-major with w_norm folded in.
        //      item = float4 = (2 k-rows) x (2 d's). 12 k2-groups x 64 pairs.
#pragma unroll
        for (int it = 0; it < 3; it++) {
            int idx = it * NTHREADS + t;
            int p   = idx & 63;        // d-pair
            int k2  = idx >> 6;        // 0..11
            int ka = 2 * k2, kb = 2 * k2 + 1;
            const float* ra = (ka < 4) ? (Wpre  + (size_t)ka * D_TOTAL)
                            : (ka < 8) ? (Wpost + (size_t)(ka - 4) * D_TOTAL)
                                       : (Wres  + (size_t)(ka - 8) * D_TOTAL);
            const float* rb = (kb < 4) ? (Wpre  + (size_t)kb * D_TOTAL)
                            : (kb < 8) ? (Wpost + (size_t)(kb - 4) * D_TOTAL)
                                       : (Wres  + (size_t)(kb - 8) * D_TOTAL);
            float2 wv = *(const float2*)(wn + d0 + 2 * p);
            float2 a  = *(const float2*)(ra + d0 + 2 * p);
            float2 bb = *(const float2*)(rb + d0 + 2 * p);
            float4 o;
            o.x = a.x  * wv.x;  o.y = a.y  * wv.y;
            o.z = bb.x * wv.x;  o.w = bb.y * wv.y;
            *(float4*)(ws + p * WPITCH + 4 * k2) = o;
        }
        __syncthreads();

        // ---- compute: 16 d-pair steps per warp
        const unsigned long long* xp0 =
            (const unsigned long long*)(xs + lane * XPITCH + 32 * dg);
        const unsigned long long* xp1 =
            (const unsigned long long*)(xs + (lane + 32) * XPITCH + 32 * dg);
        const ulonglong2* wp =
            (const ulonglong2*)(ws + (dg * 16) * WPITCH + kg * 24);
#pragma unroll
        for (int i = 0; i < 16; i++) {
            unsigned long long xa = xp0[i];
            unsigned long long xb = xp1[i];
            ulonglong2 w0 = wp[i * (WPITCH / 4) + 0];
            ulonglong2 w1 = wp[i * (WPITCH / 4) + 1];
            ulonglong2 w2 = wp[i * (WPITCH / 4) + 2];
            ulonglong2 w3 = wp[i * (WPITCH / 4) + 3];
            ulonglong2 w4 = wp[i * (WPITCH / 4) + 4];
            ulonglong2 w5 = wp[i * (WPITCH / 4) + 5];
            FFMA2(acc[0],  xa, w0.x); FFMA2(acc[1],  xa, w0.y);
            FFMA2(acc[2],  xa, w1.x); FFMA2(acc[3],  xa, w1.y);
            FFMA2(acc[4],  xa, w2.x); FFMA2(acc[5],  xa, w2.y);
            FFMA2(acc[6],  xa, w3.x); FFMA2(acc[7],  xa, w3.y);
            FFMA2(acc[8],  xa, w4.x); FFMA2(acc[9],  xa, w4.y);
            FFMA2(acc[10], xa, w5.x); FFMA2(acc[11], xa, w5.y);
            FFMA2(acc[12], xb, w0.x); FFMA2(acc[13], xb, w0.y);
            FFMA2(acc[14], xb, w1.x); FFMA2(acc[15], xb, w1.y);
            FFMA2(acc[16], xb, w2.x); FFMA2(acc[17], xb, w2.y);
            FFMA2(acc[18], xb, w3.x); FFMA2(acc[19], xb, w3.y);
            FFMA2(acc[20], xb, w4.x); FFMA2(acc[21], xb, w4.y);
            FFMA2(acc[22], xb, w5.x); FFMA2(acc[23], xb, w5.y);
            if (kg == 0) { FFMA2(ss0, xa, xa); FFMA2(ss1, xb, xb); }
        }
    }

    // ---- block reduction over dg (4 warps per kg), f32x2 halves folded
    __syncthreads();
    float* red = xs;   // reuse: 256 * 26 = 6656 floats < 8320
    {
        int base = t * 26;
#pragma unroll
        for (int j = 0; j < 24; j++) red[base + j] = fold2(acc[j]);
        red[base + 24] = fold2(ss0);
        red[base + 25] = fold2(ss1);
    }
    __syncthreads();
    if (t < 64) {
        int kg2 = t >> 5, ln = t & 31;
        float* dst = g_partial + (size_t)blockIdx.x * (BATCH * NJ);
#pragma unroll
        for (int j = 0; j < 12; j++) {
            float s0 = 0.f, s1 = 0.f;
#pragma unroll
            for (int d2 = 0; d2 < 4; d2++) {
                int ww = d2 * 2 + kg2;
                s0 += red[(ww * 32 + ln) * 26 + j];
                s1 += red[(ww * 32 + ln) * 26 + 12 + j];
            }
            int k = kg2 * 12 + j;
            dst[ln * NJ + k]        = s0;
            dst[(ln + 32) * NJ + k] = s1;
        }
        if (kg2 == 0) {
            float s0 = 0.f, s1 = 0.f;
#pragma unroll
            for (int d2 = 0; d2 < 4; d2++) {
                int ww = d2 * 2;
                s0 += red[(ww * 32 + ln) * 26 + 24];
                s1 += red[(ww * 32 + ln) * 26 + 25];
            }
            dst[ln * NJ + 24]        = s0;
            dst[(ln + 32) * NJ + 24] = s1;
        }
    }
}

__global__ void finalize_kernel(const float* __restrict__ b_pre, const float* __restrict__ b_post,
                                const float* __restrict__ b_res, const float* __restrict__ a_pre,
                                const float* __restrict__ a_post, const float* __restrict__ a_res,
                                float* __restrict__ out)
{
    const int b = blockIdx.x;
    const int t = threadIdx.x;
    __shared__ float sum4[NJ][4];
    __shared__ float v[NJ];

    if (t < NJ * 4) {
        int j = t >> 2, s = t & 3;
        float a = 0.f;
        for (int blk = s; blk < NBLK; blk += 4)
            a += g_partial[(size_t)blk * (BATCH * NJ) + b * NJ + j];
        sum4[j][s] = a;
    }
    __syncthreads();
    if (t < NJ) v[t] = sum4[t][0] + sum4[t][1] + sum4[t][2] + sum4[t][3];
    __syncthreads();

    if (t < 16) {
        // ms = mean(x^2); eps = FLT_EPSILON (torch RMSNorm eps=None semantics)
        float rinv = rsqrtf(v[24] * (1.0f / (float)D_TOTAL) + 1.1920929e-7f);
        if (t < 4) {
            float p = a_pre[0] * (v[t] * rinv) + b_pre[t];
            out[b * 4 + t] = 1.f / (1.f + __expf(-p));
            float q = a_post[0] * (v[4 + t] * rinv) + b_post[t];
            out[256 + b * 4 + t] = 2.f / (1.f + __expf(-q));
        }
        // Sinkhorn on a 4x4, lanes t = i*4 + j
        float r = a_res[0] * (v[8 + t] * rinv) + b_res[t];
        float m = r;
        m = fmaxf(m, __shfl_xor_sync(0xffffu, m, 1));
        m = fmaxf(m, __shfl_xor_sync(0xffffu, m, 2));
        float M = __expf(r - m);
#pragma unroll
        for (int it = 0; it < 20; it++) {
            float rs = M + __shfl_xor_sync(0xffffu, M, 1);
            rs += __shfl_xor_sync(0xffffu, rs, 2);
            M = __fdividef(M, rs + 1e-6f);
            float cs = M + __shfl_xor_sync(0xffffu, M, 4);
            cs += __shfl_xor_sync(0xffffu, cs, 8);
            M = __fdividef(M, cs + 1e-6f);
        }
        out[512 + b * 16 + t] = M;
    }
}

extern "C" void kernel_launch(void* const* d_in, const int* in_sizes, int n_in,
                              void* d_out, int out_size)
{
    const float* x     = (const float*)d_in[0];
    const float* wnorm = (const float*)d_in[1];
    const float* Wpre  = (const float*)d_in[2];
    const float* Wpost = (const float*)d_in[3];
    const float* Wres  = (const float*)d_in[4];
    const float* bpre  = (const float*)d_in[5];
    const float* bpost = (const float*)d_in[6];
    const float* bres  = (const float*)d_in[7];
    const float* apre  = (const float*)d_in[8];
    const float* apost = (const float*)d_in[9];
    const float* ares  = (const float*)d_in[10];
    float* out = (float*)d_out;

    dot_kernel<<<NBLK, NTHREADS>>>(x, wnorm, Wpre, Wpost, Wres);
    finalize_kernel<<<BATCH, 128>>>(bpre, bpost, bres, apre, apost, ares, out);
}

// round 3
// speedup vs baseline: 1.1374x; 1.1374x over previous
#include <cuda_runtime.h>
#include <cstdint>
#include <cstddef>

#define D_TOTAL   786432
#define TILE      64
#define N_TILES   (D_TOTAL / TILE)   // 12288
#define BATCH     64
#define XPITCH    66                 // floats per x smem row
#define WPITCH    52                 // floats per W smem row (24 k * 2 + pad, 16B aligned)
#define NBLK      296
#define NTHREADS  256
#define NJ        25                 // 24 dots + sumsq
// per-buffer float counts / offsets
#define XS_OFF    0
#define WS_OFF    (BATCH * XPITCH)               // 4224
#define WN_OFF    (BATCH * XPITCH + 32 * WPITCH) // 5888
#define BUF       (WN_OFF + TILE)                // 5952 floats = 23808 B

// partial results, layout [b][j][blk] for coalesced finalize reads
__device__ float g_partial[BATCH * NJ * NBLK];

typedef unsigned long long ull;

__device__ __forceinline__ float fold2(ull v) {
    return __uint_as_float((unsigned)v) + __uint_as_float((unsigned)(v >> 32));
}
__device__ __forceinline__ unsigned smem_u32(const void* p) {
    return (unsigned)__cvta_generic_to_shared(p);
}
#define FFMA2(accv, av, bv) asm("fma.rn.f32x2 %0, %1, %2, %0;" : "+l"(accv) : "l"(av), "l"(bv))
#define FMUL2(dv, av, bv)   asm("mul.rn.f32x2 %0, %1, %2;" : "=l"(dv) : "l"(av), "l"(bv))
#define CPA8(d, s)   asm volatile("cp.async.ca.shared.global [%0], [%1], 8;" :: "r"(d), "l"(s))
#define CPCOMMIT()   asm volatile("cp.async.commit_group;")
#define CPWAIT1()    asm volatile("cp.async.wait_group 1;")
#define CPWAIT0()    asm volatile("cp.async.wait_group 0;")

__global__ void __launch_bounds__(NTHREADS, 2)
dot_kernel(const float* __restrict__ x, const float* __restrict__ wn,
           const float* __restrict__ Wpre, const float* __restrict__ Wpost,
           const float* __restrict__ Wres)
{
    __shared__ float sb[2][BUF];    // 47616 B static

    const int t    = threadIdx.x;
    const int lane = t & 31;
    const int w    = t >> 5;
    const int kg   = w & 1;    // k-group: k = kg*12 .. +11
    const int dg   = w >> 1;   // d-group: pairs dg*8 .. +7

    ull acc[24];               // [b2*12 + j]
#pragma unroll
    for (int i = 0; i < 24; i++) acc[i] = 0ull;
    ull ss0 = 0ull, ss1 = 0ull;

    // staging lambda: issue cp.async for one tile into buffer bsel
    auto stage = [&](int bsel, int tile) {
        float* s = sb[bsel];
        const int d0 = tile * TILE;
        // x: 64 rows x 32 float2 -> 8 ops/thread, coalesced (warp covers one row)
#pragma unroll
        for (int it = 0; it < 8; it++) {
            int idx = it * NTHREADS + t;
            int d2  = idx & 31;
            int row = idx >> 5;
            CPA8(smem_u32(s + XS_OFF + row * XPITCH + 2 * d2),
                 x + (size_t)row * D_TOTAL + d0 + 2 * d2);
        }
        // W raw: 24 k-rows x 32 d-pairs -> 3 ops/thread, p-major for coalescing
#pragma unroll
        for (int it = 0; it < 3; it++) {
            int idx = it * NTHREADS + t;
            int p   = idx & 31;
            int k   = idx >> 5;     // 0..23
            const float* r = (k < 4) ? (Wpre  + (size_t)k * D_TOTAL)
                           : (k < 8) ? (Wpost + (size_t)(k - 4) * D_TOTAL)
                                     : (Wres  + (size_t)(k - 8) * D_TOTAL);
            CPA8(smem_u32(s + WS_OFF + p * WPITCH + 2 * k), r + d0 + 2 * p);
        }
        // w_norm: 32 float2
        if (t < 32) CPA8(smem_u32(s + WN_OFF + 2 * t), wn + d0 + 2 * t);
    };

    int tile = blockIdx.x;
    stage(0, tile);
    CPCOMMIT();
    int buf = 0;

    for (; tile < N_TILES; tile += NBLK) {
        int nt = tile + NBLK;
        if (nt < N_TILES) { stage(buf ^ 1, nt); CPCOMMIT(); CPWAIT1(); }
        else              { CPWAIT0(); }
        __syncthreads();

        const float* s = sb[buf];
        const ull* xp0 = (const ull*)(s + XS_OFF + lane * XPITCH) + 8 * dg;
        const ull* xp1 = (const ull*)(s + XS_OFF + (lane + 32) * XPITCH) + 8 * dg;
        const ulonglong2* wp = (const ulonglong2*)(s + WS_OFF + (dg * 8) * WPITCH + kg * 24);
        const ull* wnp = (const ull*)(s + WN_OFF) + 8 * dg;
#pragma unroll
        for (int i = 0; i < 8; i++) {
            ull xa = xp0[i];
            ull xb = xp1[i];
            ull wv = wnp[i];
            ull xan, xbn;
            FMUL2(xan, xa, wv);
            FMUL2(xbn, xb, wv);
            ulonglong2 w0 = wp[i * 13 + 0];
            ulonglong2 w1 = wp[i * 13 + 1];
            ulonglong2 w2 = wp[i * 13 + 2];
            ulonglong2 w3 = wp[i * 13 + 3];
            ulonglong2 w4 = wp[i * 13 + 4];
            ulonglong2 w5 = wp[i * 13 + 5];
            FFMA2(acc[0],  xan, w0.x); FFMA2(acc[1],  xan, w0.y);
            FFMA2(acc[2],  xan, w1.x); FFMA2(acc[3],  xan, w1.y);
            FFMA2(acc[4],  xan, w2.x); FFMA2(acc[5],  xan, w2.y);
            FFMA2(acc[6],  xan, w3.x); FFMA2(acc[7],  xan, w3.y);
            FFMA2(acc[8],  xan, w4.x); FFMA2(acc[9],  xan, w4.y);
            FFMA2(acc[10], xan, w5.x); FFMA2(acc[11], xan, w5.y);
            FFMA2(acc[12], xbn, w0.x); FFMA2(acc[13], xbn, w0.y);
            FFMA2(acc[14], xbn, w1.x); FFMA2(acc[15], xbn, w1.y);
            FFMA2(acc[16], xbn, w2.x); FFMA2(acc[17], xbn, w2.y);
            FFMA2(acc[18], xbn, w3.x); FFMA2(acc[19], xbn, w3.y);
            FFMA2(acc[20], xbn, w4.x); FFMA2(acc[21], xbn, w4.y);
            FFMA2(acc[22], xbn, w5.x); FFMA2(acc[23], xbn, w5.y);
            if (kg == 0) { FFMA2(ss0, xa, xa); FFMA2(ss1, xb, xb); }
        }
        __syncthreads();
        buf ^= 1;
    }

    // ---- block reduction over dg (4 warps per kg), f32x2 halves folded
    __syncthreads();
    float* red = &sb[0][0];   // 11904 floats available, need 6656
    {
        int base = t * 26;
#pragma unroll
        for (int j = 0; j < 24; j++) red[base + j] = fold2(acc[j]);
        red[base + 24] = fold2(ss0);
        red[base + 25] = fold2(ss1);
    }
    __syncthreads();
    if (t < 64) {
        int kg2 = t >> 5, ln = t & 31;
#pragma unroll
        for (int j = 0; j < 12; j++) {
            float s0 = 0.f, s1 = 0.f;
#pragma unroll
            for (int d2 = 0; d2 < 4; d2++) {
                int ww = d2 * 2 + kg2;
                s0 += red[(ww * 32 + ln) * 26 + j];
                s1 += red[(ww * 32 + ln) * 26 + 12 + j];
            }
            int k = kg2 * 12 + j;
            g_partial[((size_t)ln * NJ + k) * NBLK + blockIdx.x]        = s0;
            g_partial[((size_t)(ln + 32) * NJ + k) * NBLK + blockIdx.x] = s1;
        }
        if (kg2 == 0) {
            float s0 = 0.f, s1 = 0.f;
#pragma unroll
            for (int d2 = 0; d2 < 4; d2++) {
                int ww = d2 * 2;
                s0 += red[(ww * 32 + ln) * 26 + 24];
                s1 += red[(ww * 32 + ln) * 26 + 25];
            }
            g_partial[((size_t)ln * NJ + 24) * NBLK + blockIdx.x]        = s0;
            g_partial[((size_t)(ln + 32) * NJ + 24) * NBLK + blockIdx.x] = s1;
        }
    }
}

__global__ void finalize_kernel(const float* __restrict__ b_pre, const float* __restrict__ b_post,
                                const float* __restrict__ b_res, const float* __restrict__ a_pre,
                                const float* __restrict__ a_post, const float* __restrict__ a_res,
                                float* __restrict__ out)
{
    const int b = blockIdx.x;
    const int t = threadIdx.x;
    __shared__ float part[NJ][8];
    __shared__ float v[NJ];

    if (t < NJ * 8) {
        int j = t >> 3, s = t & 7;
        const float* src = g_partial + ((size_t)b * NJ + j) * NBLK;
        float a = 0.f;
        for (int m = s; m < NBLK; m += 8) a += src[m];
        part[j][s] = a;
    }
    __syncthreads();
    if (t < NJ) {
        float a = 0.f;
#pragma unroll
        for (int s = 0; s < 8; s++) a += part[t][s];
        v[t] = a;
    }
    __syncthreads();

    if (t < 16) {
        // ms = mean(x^2); eps = FLT_EPSILON (torch RMSNorm eps=None semantics)
        float rinv = rsqrtf(v[24] * (1.0f / (float)D_TOTAL) + 1.1920929e-7f);
        if (t < 4) {
            float p = a_pre[0] * (v[t] * rinv) + b_pre[t];
            out[b * 4 + t] = 1.f / (1.f + __expf(-p));
            float q = a_post[0] * (v[4 + t] * rinv) + b_post[t];
            out[256 + b * 4 + t] = 2.f / (1.f + __expf(-q));
        }
        // Sinkhorn on a 4x4, lanes t = i*4 + j
        float r = a_res[0] * (v[8 + t] * rinv) + b_res[t];
        float m = r;
        m = fmaxf(m, __shfl_xor_sync(0xffffu, m, 1));
        m = fmaxf(m, __shfl_xor_sync(0xffffu, m, 2));
        float M = __expf(r - m);
#pragma unroll
        for (int it = 0; it < 20; it++) {
            float rs = M + __shfl_xor_sync(0xffffu, M, 1);
            rs += __shfl_xor_sync(0xffffu, rs, 2);
            M = __fdividef(M, rs + 1e-6f);
            float cs = M + __shfl_xor_sync(0xffffu, M, 4);
            cs += __shfl_xor_sync(0xffffu, cs, 8);
            M = __fdividef(M, cs + 1e-6f);
        }
        out[512 + b * 16 + t] = M;
    }
}

extern "C" void kernel_launch(void* const* d_in, const int* in_sizes, int n_in,
                              void* d_out, int out_size)
{
    const float* x     = (const float*)d_in[0];
    const float* wnorm = (const float*)d_in[1];
    const float* Wpre  = (const float*)d_in[2];
    const float* Wpost = (const float*)d_in[3];
    const float* Wres  = (const float*)d_in[4];
    const float* bpre  = (const float*)d_in[5];
    const float* bpost = (const float*)d_in[6];
    const float* bres  = (const float*)d_in[7];
    const float* apre  = (const float*)d_in[8];
    const float* apost = (const float*)d_in[9];
    const float* ares  = (const float*)d_in[10];
    float* out = (float*)d_out;

    dot_kernel<<<NBLK, NTHREADS>>>(x, wnorm, Wpre, Wpost, Wres);
    finalize_kernel<<<BATCH, 256>>>(bpre, bpost, bres, apre, apost, ares, out);
}